// round 15
// baseline (speedup 1.0000x reference)
#include <cuda_runtime.h>

#define NN 3000
#define TT 20
#define IND 6
#define HD 64
#define NH 8
#define MAXNZ 512

#define CB_WARPS 8
#define CB_WSZ  (6 * HD * HD)                       // 24576 floats of weights
#define CB_SMEM ((CB_WSZ + CB_WARPS * 12 * HD) * 4) // 120 KB

// ---------------- scratch (no allocation allowed) ----------------
__device__ ulonglong2 g_Whh4[(HD / 2) * 192];  // [kpair][row] -> (pk(w_k), pk(w_{k+1}))
__device__ float g_support[NN * HD];        // GRU final hidden
__device__ float g_s[2][NN * HD];           // per-graph head features  [n][h*8+f]
__device__ float g_f1[2][NH * NN];          // source scores  [g][h*N+n]
__device__ float g_f2[2][NH * NN];          // dest scores    [g][h*N+n]
__device__ unsigned g_f1maxI[16];           // encoded global per-(g,h) max of f1
__device__ float g_att[2][NN * HD];         // attention outputs
__device__ float g_emb[NN * HD];            // pre-pairnorm embedding
__device__ float g_colsum[HD];              // column sums for pairnorm mean

__device__ __forceinline__ float sigm(float x) { return 1.0f / (1.0f + __expf(-x)); }
__device__ __forceinline__ float tanhfast(float x) { return 2.0f * sigm(2.0f * x) - 1.0f; }

__device__ __forceinline__ unsigned fenc(float f) {
    unsigned u = __float_as_uint(f);
    return (u & 0x80000000u) ? ~u : (u | 0x80000000u);
}
__device__ __forceinline__ float fdec(unsigned u) {
    return __uint_as_float((u & 0x80000000u) ? (u & 0x7fffffffu) : ~u);
}

__device__ __forceinline__ unsigned long long pk(float lo, float hi) {
    unsigned long long r;
    asm("mov.b64 %0, {%1,%2};" : "=l"(r) : "f"(lo), "f"(hi));
    return r;
}
__device__ __forceinline__ void upk(unsigned long long v, float& lo, float& hi) {
    asm("mov.b64 {%0,%1}, %2;" : "=f"(lo), "=f"(hi) : "l"(v));
}
__device__ __forceinline__ void ffma2(unsigned long long& d, unsigned long long a, unsigned long long b) {
    asm("fma.rn.f32x2 %0, %1, %2, %0;" : "+l"(d) : "l"(a), "l"(b));
}

// ---------------- K0: pack Whh into k-pair LDG.128 layout + init reductions ----------------
__global__ void prep_kernel(const float* __restrict__ Whh) {
    int i = blockIdx.x * 256 + threadIdx.x;
    if (i < 192 * HD) {
        int r = i >> 6, k = i & 63;
        float w = Whh[i];
        unsigned long long pw = pk(w, w);
        if (k & 1) g_Whh4[(k >> 1) * 192 + r].y = pw;
        else       g_Whh4[(k >> 1) * 192 + r].x = pw;
    }
    if (blockIdx.x == 0 && threadIdx.x < HD) g_colsum[threadIdx.x] = 0.f;
    if (blockIdx.x == 0 && threadIdx.x < 16) g_f1maxI[threadIdx.x] = 0u;
}

// ---------------- K1: GRU (4 nodes / 64-thread block), PDL over prep ----------------
__global__ void __launch_bounds__(64) gru_kernel(
        const float* __restrict__ x, const float* __restrict__ Wih,
        const float* __restrict__ bih, const float* __restrict__ bhh,
        const float* __restrict__ Wp, const float* __restrict__ Wn,
        const float* __restrict__ Wup, const float* __restrict__ Wvp,
        const float* __restrict__ Wun, const float* __restrict__ Wvn) {
    __shared__ float4 shh4[2][HD];      // ping-pong: [buf][k] -> 4 nodes hidden
    __shared__ float shx[TT * IND * 4]; // [ (t*6+c)*4 + b ]
    int j = threadIdx.x;
    int node0 = blockIdx.x * 4;         // 750 blocks

#pragma unroll
    for (int e = j; e < TT * IND * 4; e += 64) {
        int b = e / (TT * IND), rem = e % (TT * IND);
        shx[rem * 4 + b] = x[node0 * (TT * IND) + e];
    }

    unsigned long long pwr[IND], pwz[IND], pwn[IND];
#pragma unroll
    for (int c = 0; c < IND; c++) {
        float a = Wih[j * IND + c];
        float b = Wih[(64 + j) * IND + c];
        float d = Wih[(128 + j) * IND + c];
        pwr[c] = pk(a, a); pwz[c] = pk(b, b); pwn[c] = pk(d, d);
    }
    float br  = bih[j] + bhh[j];
    float bz  = bih[64 + j] + bhh[64 + j];
    float bin = bih[128 + j];
    float bhn = bhh[128 + j];
    unsigned long long pbr = pk(br, br), pbz = pk(bz, bz);
    unsigned long long pbi = pk(bin, bin), pbh = pk(bhn, bhn);

    shh4[0][j] = make_float4(0.f, 0.f, 0.f, 0.f);
    float h0 = 0.f, h1 = 0.f, h2 = 0.f, h3 = 0.f;
    int cur = 0;

    cudaGridDependencySynchronize();    // g_Whh4 ready (prep done)
    __syncthreads();

    for (int t = 0; t < TT; t++) {
        const float4* xt = (const float4*)(shx + t * IND * 4);

        unsigned long long ar01 = pbr, ar23 = pbr;
        unsigned long long az01 = pbz, az23 = pbz;
        unsigned long long an01 = pbi, an23 = pbi;
        unsigned long long gn01 = pbh, gn23 = pbh;

#pragma unroll
        for (int c = 0; c < IND; c++) {
            float4 xv = xt[c];
            unsigned long long x01 = pk(xv.x, xv.y), x23 = pk(xv.z, xv.w);
            ffma2(ar01, pwr[c], x01); ffma2(ar23, pwr[c], x23);
            ffma2(az01, pwz[c], x01); ffma2(az23, pwz[c], x23);
            ffma2(an01, pwn[c], x01); ffma2(an23, pwn[c], x23);
        }

        const float4* hbuf = shh4[cur];
#pragma unroll 4
        for (int p = 0; p < HD / 2; p++) {
            float4 hva = hbuf[2 * p], hvb = hbuf[2 * p + 1];
            unsigned long long ha01 = pk(hva.x, hva.y), ha23 = pk(hva.z, hva.w);
            unsigned long long hb01 = pk(hvb.x, hvb.y), hb23 = pk(hvb.z, hvb.w);
            ulonglong2 wr = g_Whh4[p * 192 + j];
            ulonglong2 wz = g_Whh4[p * 192 + 64 + j];
            ulonglong2 wn_ = g_Whh4[p * 192 + 128 + j];
            ffma2(ar01, wr.x, ha01);  ffma2(ar23, wr.x, ha23);
            ffma2(az01, wz.x, ha01);  ffma2(az23, wz.x, ha23);
            ffma2(gn01, wn_.x, ha01); ffma2(gn23, wn_.x, ha23);
            ffma2(ar01, wr.y, hb01);  ffma2(ar23, wr.y, hb23);
            ffma2(az01, wz.y, hb01);  ffma2(az23, wz.y, hb23);
            ffma2(gn01, wn_.y, hb01); ffma2(gn23, wn_.y, hb23);
        }

        float a0, a1, a2, a3, z0, z1, z2, z3, n0, n1, n2, n3, g0, g1, g2, g3;
        upk(ar01, a0, a1); upk(ar23, a2, a3);
        upk(az01, z0, z1); upk(az23, z2, z3);
        upk(an01, n0, n1); upk(an23, n2, n3);
        upk(gn01, g0, g1); upk(gn23, g2, g3);

        float r0 = sigm(a0), r1 = sigm(a1), r2 = sigm(a2), r3 = sigm(a3);
        float zz0 = sigm(z0), zz1 = sigm(z1), zz2 = sigm(z2), zz3 = sigm(z3);
        float nv0 = tanhfast(n0 + r0 * g0);
        float nv1 = tanhfast(n1 + r1 * g1);
        float nv2 = tanhfast(n2 + r2 * g2);
        float nv3 = tanhfast(n3 + r3 * g3);
        h0 = (1.f - zz0) * nv0 + zz0 * h0;
        h1 = (1.f - zz1) * nv1 + zz1 * h1;
        h2 = (1.f - zz2) * nv2 + zz2 * h2;
        h3 = (1.f - zz3) * nv3 + zz3 * h3;
        shh4[cur ^ 1][j] = make_float4(h0, h1, h2, h3);
        __syncthreads();
        cur ^= 1;
    }

    g_support[(node0 + 0) * HD + j] = h0;
    g_support[(node0 + 1) * HD + j] = h1;
    g_support[(node0 + 2) * HD + j] = h2;
    g_support[(node0 + 3) * HD + j] = h3;

    // fused head projection: s = h @ W, f1/f2, global f1 max
    int hh = j >> 3, f = j & 7;
    const float* hsm = (const float*)shh4[cur];
#pragma unroll
    for (int g = 0; g < 2; g++) {
        const float* W  = g ? Wn  : Wp;
        float wu = (g ? Wun : Wup)[hh * 8 + f];
        float wv = (g ? Wvn : Wvp)[hh * 8 + f];
        float acc[4] = {0.f, 0.f, 0.f, 0.f};
#pragma unroll 4
        for (int k = 0; k < HD; k++) {
            float w = W[k * HD + j];
#pragma unroll
            for (int b = 0; b < 4; b++) acc[b] += hsm[k * 4 + b] * w;
        }
#pragma unroll
        for (int b = 0; b < 4; b++) {
            int n = node0 + b;
            g_s[g][n * HD + j] = acc[b];
            float t1 = acc[b] * wu, t2 = acc[b] * wv;
#pragma unroll
            for (int o = 4; o; o >>= 1) {
                t1 += __shfl_xor_sync(0xffffffffu, t1, o);
                t2 += __shfl_xor_sync(0xffffffffu, t2, o);
            }
            if (f == 0) {
                g_f1[g][hh * NN + n] = t1;
                g_f2[g][hh * NN + n] = t2;
                atomicMax(&g_f1maxI[g * 8 + hh], fenc(t1));
            }
        }
    }
}

// ---------------- K3: sparse masked attention; compaction overlapped with GRU via PDL ----------------
__global__ void attn_kernel(const float* __restrict__ adj0, const float* __restrict__ adj1) {
    int i = blockIdx.x, g = blockIdx.y;
    const float* row = (g ? adj1 : adj0) + (size_t)i * NN;
    __shared__ short idx[MAXNZ];
    __shared__ int cnts[8];
    int tid = threadIdx.x, warp = tid >> 5, lane = tid & 31;

    // pre-sync: depends only on the adjacency input
    const float4* row4 = (const float4*)row;
    float4 v[3];
#pragma unroll
    for (int it = 0; it < 3; it++) {
        int q = it * 256 + tid;
        v[it] = (q < NN / 4) ? row4[q] : make_float4(0.f, 0.f, 0.f, 0.f);
    }

    unsigned bal[12];
    int wcnt = 0;
#pragma unroll
    for (int it = 0; it < 3; it++) {
#pragma unroll
        for (int c = 0; c < 4; c++) {
            float val = (c == 0) ? v[it].x : (c == 1) ? v[it].y : (c == 2) ? v[it].z : v[it].w;
            unsigned b = __ballot_sync(0xffffffffu, val != 0.f);
            bal[it * 4 + c] = b;
            wcnt += __popc(b);
        }
    }
    if (lane == 0) cnts[warp] = wcnt;
    __syncthreads();

    int base = 0, m = 0;
#pragma unroll
    for (int s = 0; s < 8; s++) {
        int cs = cnts[s];
        if (s < warp) base += cs;
        m += cs;
    }
    m = min(m, MAXNZ);

    unsigned ltmask = (1u << lane) - 1u;
    int off = base;
#pragma unroll
    for (int it = 0; it < 3; it++) {
        int q = it * 256 + tid;
#pragma unroll
        for (int c = 0; c < 4; c++) {
            unsigned b = bal[it * 4 + c];
            if (b) {
                float val = (c == 0) ? v[it].x : (c == 1) ? v[it].y : (c == 2) ? v[it].z : v[it].w;
                if (val != 0.f) {
                    int p = off + __popc(b & ltmask);
                    if (p < MAXNZ) idx[p] = (short)(4 * q + c);
                }
                off += __popc(b);
            }
        }
    }
    __syncthreads();

    // wait for GRU outputs, then gather (transposed: 4 neighbors/iter, 8 lanes each)
    cudaGridDependencySynchronize();

    int h = warp;
    int grp = lane >> 3, f = lane & 7;
    const float* f1h = g_f1[g] + h * NN;
    float f2v = g_f2[g][h * NN + i];
    float Mv = fdec(g_f1maxI[g * 8 + h]) + f2v;
    Mv = Mv >= 0.f ? Mv : 0.2f * Mv;
    const float* sb = g_s[g];

    float accf = 0.f;
    float se = 0.f;
    for (int k = grp; k < m; k += 4) {
        int jj = idx[k];
        float vv = f1h[jj] + f2v;
        vv = vv >= 0.f ? vv : 0.2f * vv;
        float e = __expf(vv - Mv);
        float sv = sb[jj * HD + h * 8 + f];
        accf += e * sv;
        se += (f == 0) ? e : 0.f;
    }
    accf += __shfl_xor_sync(0xffffffffu, accf, 8);
    accf += __shfl_xor_sync(0xffffffffu, accf, 16);
    se += __shfl_xor_sync(0xffffffffu, se, 8);
    se += __shfl_xor_sync(0xffffffffu, se, 16);
    se = __shfl_sync(0xffffffffu, se, 0);
    if (lane < 8) {
        float inv = se > 0.f ? 1.0f / se : 0.f;
        g_att[g][i * HD + h * 8 + lane] = accf * inv;
    }
}

// ---------------- K4: comb with smem-staged weights (8 warps, 32 nodes/block, grid 94) ----------------
__global__ void __launch_bounds__(256) comb_kernel(
        const float* __restrict__ pos_b, const float* __restrict__ pWp, const float* __restrict__ pbp,
        const float* __restrict__ neg_b, const float* __restrict__ pWn, const float* __restrict__ pbn,
        const float* __restrict__ selfW, const float* __restrict__ selfb,
        const float* __restrict__ mpW, const float* __restrict__ mpb,
        const float* __restrict__ mnW, const float* __restrict__ mnb,
        const float* __restrict__ semW1, const float* __restrict__ semb1,
        const float* __restrict__ semW2) {
    extern __shared__ float smw[];                 // [6*HD*HD] weights | staging
    __shared__ float colacc[HD];
    int tid = threadIdx.x, warp = tid >> 5, lane = tid & 31;
    int c0 = 2 * lane, c1 = 2 * lane + 1;

    if (tid < HD) colacc[tid] = 0.f;

    // ---- pre-sync: stage all six 64x64 weight matrices into smem ----
    {
        const float* srcs[6] = { pWp, pWn, selfW, mpW, mnW, semW1 };
#pragma unroll
        for (int mtx = 0; mtx < 6; mtx++) {
            const float4* s4 = (const float4*)srcs[mtx];
            float4* d4 = (float4*)(smw + mtx * HD * HD);
            for (int i = tid; i < HD * HD / 4; i += 256) d4[i] = s4[i];
        }
    }
    // biases are kernel params — safe pre-sync
    float2 pb2  = ((const float2*)pos_b)[lane];
    float2 pbp2 = ((const float2*)pbp)[lane];
    float2 nb2  = ((const float2*)neg_b)[lane];
    float2 pbn2 = ((const float2*)pbn)[lane];
    float2 sfb2 = ((const float2*)selfb)[lane];
    float2 mpb2 = ((const float2*)mpb)[lane];
    float2 mnb2 = ((const float2*)mnb)[lane];
    float2 sb12 = ((const float2*)semb1)[lane];
    float2 w22  = ((const float2*)semW2)[lane];

    cudaGridDependencySynchronize();   // attn (and transitively gru) complete
    __syncthreads();                   // staged weights + colacc visible

    const float2* wp2 = (const float2*)(smw + 0 * HD * HD);
    const float2* wn2 = (const float2*)(smw + 1 * HD * HD);
    const float2* ws2 = (const float2*)(smw + 2 * HD * HD);
    const float2* wm2 = (const float2*)(smw + 3 * HD * HD);
    const float2* wq2 = (const float2*)(smw + 4 * HD * HD);
    const float2* w12 = (const float2*)(smw + 5 * HD * HD);
    float (*S)[HD] = (float(*)[HD])(smw + CB_WSZ + warp * 12 * HD);

    float colc0 = 0.f, colc1 = 0.f;
#pragma unroll
    for (int it = 0; it < 2; it++) {
        int nA = blockIdx.x * 32 + it * 16 + warp * 2;
        if (nA >= NN) continue;        // nA even, so nB=nA+1 < NN whenever nA < NN
        int nB = nA + 1;

        {
            float2 sA = ((const float2*)(g_support + nA * HD))[lane];
            float2 sB = ((const float2*)(g_support + nB * HD))[lane];
            S[0][c0] = sA.x; S[0][c1] = sA.y;
            S[1][c0] = sB.x; S[1][c1] = sB.y;
        }
        __syncwarp();

        // ---- phase 1 ----
        float2 atpA = ((const float2*)(g_att[0] + nA * HD))[lane];
        float2 atpB = ((const float2*)(g_att[0] + nB * HD))[lane];
        float2 atnA = ((const float2*)(g_att[1] + nA * HD))[lane];
        float2 atnB = ((const float2*)(g_att[1] + nB * HD))[lane];
        float apA0 = atpA.x + pb2.x + pbp2.x, apA1 = atpA.y + pb2.y + pbp2.y;
        float apB0 = atpB.x + pb2.x + pbp2.x, apB1 = atpB.y + pb2.y + pbp2.y;
        float anA0 = atnA.x + nb2.x + pbn2.x, anA1 = atnA.y + nb2.y + pbn2.y;
        float anB0 = atnB.x + nb2.x + pbn2.x, anB1 = atnB.y + nb2.y + pbn2.y;
        float svA0 = sfb2.x, svA1 = sfb2.y, svB0 = sfb2.x, svB1 = sfb2.y;
#pragma unroll 8
        for (int k = 0; k < HD; k++) {
            float sA = S[0][k], sBv = S[1][k];
            float2 wp = wp2[k * 32 + lane];
            float2 wn = wn2[k * 32 + lane];
            float2 ws = ws2[k * 32 + lane];
            apA0 += sA * wp.x;  apA1 += sA * wp.y;  apB0 += sBv * wp.x;  apB1 += sBv * wp.y;
            anA0 += sA * wn.x;  anA1 += sA * wn.y;  anB0 += sBv * wn.x;  anB1 += sBv * wn.y;
            svA0 += sA * ws.x;  svA1 += sA * ws.y;  svB0 += sBv * ws.x;  svB1 += sBv * ws.y;
        }
        S[2][c0] = apA0; S[2][c1] = apA1; S[3][c0] = apB0; S[3][c1] = apB1;
        S[4][c0] = anA0; S[4][c1] = anA1; S[5][c0] = anB0; S[5][c1] = anB1;
        __syncwarp();

        // ---- phase 2 ----
        float spA0 = mpb2.x, spA1 = mpb2.y, spB0 = mpb2.x, spB1 = mpb2.y;
        float snA0 = mnb2.x, snA1 = mnb2.y, snB0 = mnb2.x, snB1 = mnb2.y;
#pragma unroll 8
        for (int k = 0; k < HD; k++) {
            float pA = S[2][k], pB = S[3][k], qA = S[4][k], qB = S[5][k];
            float2 w = wm2[k * 32 + lane];
            float2 v = wq2[k * 32 + lane];
            spA0 += pA * w.x; spA1 += pA * w.y; spB0 += pB * w.x; spB1 += pB * w.y;
            snA0 += qA * v.x; snA1 += qA * v.y; snB0 += qB * v.x; snB1 += qB * v.y;
        }
        S[6][c0] = svA0; S[6][c1] = svA1; S[7][c0] = svB0; S[7][c1] = svB1;
        S[8][c0] = spA0; S[8][c1] = spA1; S[9][c0] = spB0; S[9][c1] = spB1;
        S[10][c0] = snA0; S[10][c1] = snA1; S[11][c0] = snB0; S[11][c1] = snB1;
        __syncwarp();

        // ---- phase 3: semantic attention logits ----
        float tA00 = sb12.x, tA01 = sb12.y, tA10 = sb12.x, tA11 = sb12.y, tA20 = sb12.x, tA21 = sb12.y;
        float tB00 = sb12.x, tB01 = sb12.y, tB10 = sb12.x, tB11 = sb12.y, tB20 = sb12.x, tB21 = sb12.y;
#pragma unroll 8
        for (int k = 0; k < HD; k++) {
            float2 w = w12[k * 32 + lane];
            float e0A = S[6][k], e0B = S[7][k];
            float e1A = S[8][k], e1B = S[9][k];
            float e2A = S[10][k], e2B = S[11][k];
            tA00 += e0A * w.x; tA01 += e0A * w.y; tB00 += e0B * w.x; tB01 += e0B * w.y;
            tA10 += e1A * w.x; tA11 += e1A * w.y; tB10 += e1B * w.x; tB11 += e1B * w.y;
            tA20 += e2A * w.x; tA21 += e2A * w.y; tB20 += e2B * w.x; tB21 += e2B * w.y;
        }
        float uA0 = tanhfast(tA00) * w22.x + tanhfast(tA01) * w22.y;
        float uA1 = tanhfast(tA10) * w22.x + tanhfast(tA11) * w22.y;
        float uA2 = tanhfast(tA20) * w22.x + tanhfast(tA21) * w22.y;
        float uB0 = tanhfast(tB00) * w22.x + tanhfast(tB01) * w22.y;
        float uB1 = tanhfast(tB10) * w22.x + tanhfast(tB11) * w22.y;
        float uB2 = tanhfast(tB20) * w22.x + tanhfast(tB21) * w22.y;
#pragma unroll
        for (int o = 16; o; o >>= 1) {
            uA0 += __shfl_xor_sync(0xffffffffu, uA0, o);
            uA1 += __shfl_xor_sync(0xffffffffu, uA1, o);
            uA2 += __shfl_xor_sync(0xffffffffu, uA2, o);
            uB0 += __shfl_xor_sync(0xffffffffu, uB0, o);
            uB1 += __shfl_xor_sync(0xffffffffu, uB1, o);
            uB2 += __shfl_xor_sync(0xffffffffu, uB2, o);
        }
        float mA = fmaxf(uA0, fmaxf(uA1, uA2));
        float eA0 = __expf(uA0 - mA), eA1 = __expf(uA1 - mA), eA2 = __expf(uA2 - mA);
        float invA = 1.f / (eA0 + eA1 + eA2);
        float embA0 = (eA0 * svA0 + eA1 * spA0 + eA2 * snA0) * invA;
        float embA1 = (eA0 * svA1 + eA1 * spA1 + eA2 * snA1) * invA;
        float mB = fmaxf(uB0, fmaxf(uB1, uB2));
        float eB0 = __expf(uB0 - mB), eB1 = __expf(uB1 - mB), eB2 = __expf(uB2 - mB);
        float invB = 1.f / (eB0 + eB1 + eB2);
        float embB0 = (eB0 * svB0 + eB1 * spB0 + eB2 * snB0) * invB;
        float embB1 = (eB0 * svB1 + eB1 * spB1 + eB2 * snB1) * invB;

        ((float2*)(g_emb + nA * HD))[lane] = make_float2(embA0, embA1);
        ((float2*)(g_emb + nB * HD))[lane] = make_float2(embB0, embB1);
        colc0 += embA0 + embB0;
        colc1 += embA1 + embB1;
    }
    atomicAdd(&colacc[c0], colc0);
    atomicAdd(&colacc[c1], colc1);
    __syncthreads();
    if (tid < HD) atomicAdd(&g_colsum[tid], colacc[tid]);
}

// ---------------- K5: pairnorm + prediction head (warp per node) ----------------
__global__ void final_kernel(const float* __restrict__ predW, const float* __restrict__ predb,
                             float* __restrict__ out) {
    int warp = threadIdx.x >> 5, lane = threadIdx.x & 31;
    int n = blockIdx.x * 4 + warp;
    float invn = 1.0f / NN;
    float x0 = g_emb[n * HD + lane]      - g_colsum[lane]      * invn;
    float x1 = g_emb[n * HD + 32 + lane] - g_colsum[32 + lane] * invn;
    float ss = x0 * x0 + x1 * x1;
    float dt = x0 * predW[lane] + x1 * predW[32 + lane];
#pragma unroll
    for (int o = 16; o; o >>= 1) {
        ss += __shfl_xor_sync(0xffffffffu, ss, o);
        dt += __shfl_xor_sync(0xffffffffu, dt, o);
    }
    if (lane == 0) out[n] = sigm(dt * rsqrtf(1e-6f + ss) + predb[0]);
}

// ---------------- launch (PDL on gru/attn/comb) ----------------
template <typename... Args>
static void launch_pdl(void (*kern)(Args...), dim3 grid, dim3 block, size_t smem, Args... args) {
    cudaLaunchConfig_t cfg = {};
    cfg.gridDim = grid;
    cfg.blockDim = block;
    cfg.dynamicSmemBytes = smem;
    cfg.stream = 0;
    cudaLaunchAttribute attr[1];
    attr[0].id = cudaLaunchAttributeProgrammaticStreamSerialization;
    attr[0].val.programmaticStreamSerializationAllowed = 1;
    cfg.attrs = attr;
    cfg.numAttrs = 1;
    cudaLaunchKernelEx(&cfg, kern, args...);
}

extern "C" void kernel_launch(void* const* d_in, const int* in_sizes, int n_in,
                              void* d_out, int out_size) {
    (void)in_sizes; (void)n_in; (void)out_size;
    const float* inputs   = (const float*)d_in[0];
    const float* pos_adj  = (const float*)d_in[1];
    const float* neg_adj  = (const float*)d_in[2];
    const float* Wih      = (const float*)d_in[3];
    const float* Whh      = (const float*)d_in[4];
    const float* bih      = (const float*)d_in[5];
    const float* bhh      = (const float*)d_in[6];
    const float* pos_W    = (const float*)d_in[7];
    const float* pos_Wu   = (const float*)d_in[8];
    const float* pos_Wv   = (const float*)d_in[9];
    const float* pos_b    = (const float*)d_in[10];
    const float* pos_projW= (const float*)d_in[11];
    const float* pos_projb= (const float*)d_in[12];
    const float* neg_W    = (const float*)d_in[13];
    const float* neg_Wu   = (const float*)d_in[14];
    const float* neg_Wv   = (const float*)d_in[15];
    const float* neg_b    = (const float*)d_in[16];
    const float* neg_projW= (const float*)d_in[17];
    const float* neg_projb= (const float*)d_in[18];
    const float* self_W   = (const float*)d_in[19];
    const float* self_b   = (const float*)d_in[20];
    const float* mlpp_W   = (const float*)d_in[21];
    const float* mlpp_b   = (const float*)d_in[22];
    const float* mlpn_W   = (const float*)d_in[23];
    const float* mlpn_b   = (const float*)d_in[24];
    const float* sem_W1   = (const float*)d_in[25];
    const float* sem_b1   = (const float*)d_in[26];
    const float* sem_W2   = (const float*)d_in[27];
    const float* pred_W   = (const float*)d_in[28];
    const float* pred_b   = (const float*)d_in[29];

    static int attr_set = 0;
    if (!attr_set) {
        cudaFuncSetAttribute(comb_kernel, cudaFuncAttributeMaxDynamicSharedMemorySize, CB_SMEM);
        attr_set = 1;
    }

    prep_kernel<<<48, 256>>>(Whh);
    launch_pdl(gru_kernel, dim3(NN / 4), dim3(64), 0,
               inputs, Wih, bih, bhh,
               pos_W, neg_W, pos_Wu, pos_Wv, neg_Wu, neg_Wv);
    launch_pdl(attn_kernel, dim3(NN, 2), dim3(256), 0, pos_adj, neg_adj);
    launch_pdl(comb_kernel, dim3((NN + 31) / 32), dim3(256), (size_t)CB_SMEM,
               pos_b, pos_projW, pos_projb, neg_b, neg_projW, neg_projb,
               self_W, self_b, mlpp_W, mlpp_b, mlpn_W, mlpn_b,
               sem_W1, sem_b1, sem_W2);
    final_kernel<<<NN / 4, 128>>>(pred_W, pred_b, (float*)d_out);
}

// round 16
// speedup vs baseline: 1.1428x; 1.1428x over previous
#include <cuda_runtime.h>

#define NN 3000
#define TT 20
#define IND 6
#define HD 64
#define NH 8
#define MAXNZ 512

#define CB_WARPS 8
#define CB_WSZ  (6 * HD * HD)                       // 24576 floats of weights
#define CB_SMEM ((CB_WSZ + CB_WARPS * 12 * HD) * 4) // 120 KB

// ---------------- scratch (no allocation allowed) ----------------
__device__ float4 g_WA[(HD / 2) * HD];      // [p*64+j] = (wr_k, wr_k+1, wz_k, wz_k+1)
__device__ float2 g_WB[(HD / 2) * HD];      // [p*64+j] = (wn_k, wn_k+1)
__device__ float g_support[NN * HD];        // GRU final hidden
__device__ float g_s[2][NN * HD];           // per-graph head features  [n][h*8+f]
__device__ float g_f1[2][NH * NN];          // source scores  [g][h*N+n]
__device__ float g_f2[2][NH * NN];          // dest scores    [g][h*N+n]
__device__ unsigned g_f1maxI[16];           // encoded global per-(g,h) max of f1
__device__ float g_att[2][NN * HD];         // attention outputs
__device__ float g_emb[NN * HD];            // pre-pairnorm embedding
__device__ float g_colsum[HD];              // column sums for pairnorm mean

__device__ __forceinline__ float sigm(float x) { return 1.0f / (1.0f + __expf(-x)); }
__device__ __forceinline__ float tanhfast(float x) { return 2.0f * sigm(2.0f * x) - 1.0f; }

__device__ __forceinline__ unsigned fenc(float f) {
    unsigned u = __float_as_uint(f);
    return (u & 0x80000000u) ? ~u : (u | 0x80000000u);
}
__device__ __forceinline__ float fdec(unsigned u) {
    return __uint_as_float((u & 0x80000000u) ? (u & 0x7fffffffu) : ~u);
}

__device__ __forceinline__ unsigned long long pk(float lo, float hi) {
    unsigned long long r;
    asm("mov.b64 %0, {%1,%2};" : "=l"(r) : "f"(lo), "f"(hi));
    return r;
}
__device__ __forceinline__ void upk(unsigned long long v, float& lo, float& hi) {
    asm("mov.b64 {%0,%1}, %2;" : "=f"(lo), "=f"(hi) : "l"(v));
}
__device__ __forceinline__ void ffma2(unsigned long long& d, unsigned long long a, unsigned long long b) {
    asm("fma.rn.f32x2 %0, %1, %2, %0;" : "+l"(d) : "l"(a), "l"(b));
}

// ---------------- K0: natural-layout weight repack + init reductions ----------------
__global__ void prep_kernel(const float* __restrict__ Whh) {
    int i = blockIdx.x * 256 + threadIdx.x;
    if (i < 192 * HD) {
        int r = i >> 6, k = i & 63;
        float w = Whh[i];
        int gate = r >> 6;            // 0=r, 1=z, 2=n
        int j = r & 63;
        int p = k >> 1, odd = k & 1;
        if (gate == 0)      *(&g_WA[p * 64 + j].x + odd) = w;
        else if (gate == 1) *(&g_WA[p * 64 + j].z + odd) = w;
        else                *(&g_WB[p * 64 + j].x + odd) = w;
    }
    if (blockIdx.x == 0 && threadIdx.x < HD) g_colsum[threadIdx.x] = 0.f;
    if (blockIdx.x == 0 && threadIdx.x < 16) g_f1maxI[threadIdx.x] = 0u;
}

// ---------------- K1: GRU (4 nodes / 64-thread block), natural-weight loads + reg duplication ----------------
__global__ void __launch_bounds__(64) gru_kernel(
        const float* __restrict__ x, const float* __restrict__ Wih,
        const float* __restrict__ bih, const float* __restrict__ bhh,
        const float* __restrict__ Wp, const float* __restrict__ Wn,
        const float* __restrict__ Wup, const float* __restrict__ Wvp,
        const float* __restrict__ Wun, const float* __restrict__ Wvn) {
    __shared__ float4 shh4[2][HD];      // ping-pong: [buf][k] -> 4 nodes hidden
    __shared__ float shx[TT * IND * 4]; // [ (t*6+c)*4 + b ]
    int j = threadIdx.x;
    int node0 = blockIdx.x * 4;         // 750 blocks

#pragma unroll
    for (int e = j; e < TT * IND * 4; e += 64) {
        int b = e / (TT * IND), rem = e % (TT * IND);
        shx[rem * 4 + b] = x[node0 * (TT * IND) + e];
    }

    unsigned long long pwr[IND], pwz[IND], pwn[IND];
#pragma unroll
    for (int c = 0; c < IND; c++) {
        float a = Wih[j * IND + c];
        float b = Wih[(64 + j) * IND + c];
        float d = Wih[(128 + j) * IND + c];
        pwr[c] = pk(a, a); pwz[c] = pk(b, b); pwn[c] = pk(d, d);
    }
    float br  = bih[j] + bhh[j];
    float bz  = bih[64 + j] + bhh[64 + j];
    float bin = bih[128 + j];
    float bhn = bhh[128 + j];
    unsigned long long pbr = pk(br, br), pbz = pk(bz, bz);
    unsigned long long pbi = pk(bin, bin), pbh = pk(bhn, bhn);

    shh4[0][j] = make_float4(0.f, 0.f, 0.f, 0.f);
    float h0 = 0.f, h1 = 0.f, h2 = 0.f, h3 = 0.f;
    int cur = 0;

    cudaGridDependencySynchronize();    // g_WA/g_WB ready (prep done)
    __syncthreads();

    for (int t = 0; t < TT; t++) {
        const float4* xt = (const float4*)(shx + t * IND * 4);

        unsigned long long ar01 = pbr, ar23 = pbr;
        unsigned long long az01 = pbz, az23 = pbz;
        unsigned long long an01 = pbi, an23 = pbi;
        unsigned long long gn01 = pbh, gn23 = pbh;

#pragma unroll
        for (int c = 0; c < IND; c++) {
            float4 xv = xt[c];
            unsigned long long x01 = pk(xv.x, xv.y), x23 = pk(xv.z, xv.w);
            ffma2(ar01, pwr[c], x01); ffma2(ar23, pwr[c], x23);
            ffma2(az01, pwz[c], x01); ffma2(az23, pwz[c], x23);
            ffma2(an01, pwn[c], x01); ffma2(an23, pwn[c], x23);
        }

        const float4* hbuf = shh4[cur];
#pragma unroll 4
        for (int p = 0; p < HD / 2; p++) {
            float4 hva = hbuf[2 * p], hvb = hbuf[2 * p + 1];
            unsigned long long ha01 = pk(hva.x, hva.y), ha23 = pk(hva.z, hva.w);
            unsigned long long hb01 = pk(hvb.x, hvb.y), hb23 = pk(hvb.z, hvb.w);
            float4 wa = g_WA[p * 64 + j];
            float2 wb = g_WB[p * 64 + j];
            unsigned long long wrx = pk(wa.x, wa.x), wry = pk(wa.y, wa.y);
            unsigned long long wzx = pk(wa.z, wa.z), wzy = pk(wa.w, wa.w);
            unsigned long long wnx = pk(wb.x, wb.x), wny = pk(wb.y, wb.y);
            ffma2(ar01, wrx, ha01);  ffma2(ar23, wrx, ha23);
            ffma2(az01, wzx, ha01);  ffma2(az23, wzx, ha23);
            ffma2(gn01, wnx, ha01);  ffma2(gn23, wnx, ha23);
            ffma2(ar01, wry, hb01);  ffma2(ar23, wry, hb23);
            ffma2(az01, wzy, hb01);  ffma2(az23, wzy, hb23);
            ffma2(gn01, wny, hb01);  ffma2(gn23, wny, hb23);
        }

        float a0, a1, a2, a3, z0, z1, z2, z3, n0, n1, n2, n3, g0, g1, g2, g3;
        upk(ar01, a0, a1); upk(ar23, a2, a3);
        upk(az01, z0, z1); upk(az23, z2, z3);
        upk(an01, n0, n1); upk(an23, n2, n3);
        upk(gn01, g0, g1); upk(gn23, g2, g3);

        float r0 = sigm(a0), r1 = sigm(a1), r2 = sigm(a2), r3 = sigm(a3);
        float zz0 = sigm(z0), zz1 = sigm(z1), zz2 = sigm(z2), zz3 = sigm(z3);
        float nv0 = tanhfast(n0 + r0 * g0);
        float nv1 = tanhfast(n1 + r1 * g1);
        float nv2 = tanhfast(n2 + r2 * g2);
        float nv3 = tanhfast(n3 + r3 * g3);
        h0 = (1.f - zz0) * nv0 + zz0 * h0;
        h1 = (1.f - zz1) * nv1 + zz1 * h1;
        h2 = (1.f - zz2) * nv2 + zz2 * h2;
        h3 = (1.f - zz3) * nv3 + zz3 * h3;
        shh4[cur ^ 1][j] = make_float4(h0, h1, h2, h3);
        __syncthreads();
        cur ^= 1;
    }

    g_support[(node0 + 0) * HD + j] = h0;
    g_support[(node0 + 1) * HD + j] = h1;
    g_support[(node0 + 2) * HD + j] = h2;
    g_support[(node0 + 3) * HD + j] = h3;

    // fused head projection: s = h @ W, f1/f2, global f1 max
    int hh = j >> 3, f = j & 7;
    const float* hsm = (const float*)shh4[cur];
#pragma unroll
    for (int g = 0; g < 2; g++) {
        const float* W  = g ? Wn  : Wp;
        float wu = (g ? Wun : Wup)[hh * 8 + f];
        float wv = (g ? Wvn : Wvp)[hh * 8 + f];
        float acc[4] = {0.f, 0.f, 0.f, 0.f};
#pragma unroll 4
        for (int k = 0; k < HD; k++) {
            float w = W[k * HD + j];
#pragma unroll
            for (int b = 0; b < 4; b++) acc[b] += hsm[k * 4 + b] * w;
        }
#pragma unroll
        for (int b = 0; b < 4; b++) {
            int n = node0 + b;
            g_s[g][n * HD + j] = acc[b];
            float t1 = acc[b] * wu, t2 = acc[b] * wv;
#pragma unroll
            for (int o = 4; o; o >>= 1) {
                t1 += __shfl_xor_sync(0xffffffffu, t1, o);
                t2 += __shfl_xor_sync(0xffffffffu, t2, o);
            }
            if (f == 0) {
                g_f1[g][hh * NN + n] = t1;
                g_f2[g][hh * NN + n] = t2;
                atomicMax(&g_f1maxI[g * 8 + hh], fenc(t1));
            }
        }
    }
}

// ---------------- K3: sparse masked attention; compaction overlapped with GRU via PDL ----------------
__global__ void attn_kernel(const float* __restrict__ adj0, const float* __restrict__ adj1) {
    int i = blockIdx.x, g = blockIdx.y;
    const float* row = (g ? adj1 : adj0) + (size_t)i * NN;
    __shared__ short idx[MAXNZ];
    __shared__ int cnts[8];
    int tid = threadIdx.x, warp = tid >> 5, lane = tid & 31;

    const float4* row4 = (const float4*)row;
    float4 v[3];
#pragma unroll
    for (int it = 0; it < 3; it++) {
        int q = it * 256 + tid;
        v[it] = (q < NN / 4) ? row4[q] : make_float4(0.f, 0.f, 0.f, 0.f);
    }

    unsigned bal[12];
    int wcnt = 0;
#pragma unroll
    for (int it = 0; it < 3; it++) {
#pragma unroll
        for (int c = 0; c < 4; c++) {
            float val = (c == 0) ? v[it].x : (c == 1) ? v[it].y : (c == 2) ? v[it].z : v[it].w;
            unsigned b = __ballot_sync(0xffffffffu, val != 0.f);
            bal[it * 4 + c] = b;
            wcnt += __popc(b);
        }
    }
    if (lane == 0) cnts[warp] = wcnt;
    __syncthreads();

    int base = 0, m = 0;
#pragma unroll
    for (int s = 0; s < 8; s++) {
        int cs = cnts[s];
        if (s < warp) base += cs;
        m += cs;
    }
    m = min(m, MAXNZ);

    unsigned ltmask = (1u << lane) - 1u;
    int off = base;
#pragma unroll
    for (int it = 0; it < 3; it++) {
        int q = it * 256 + tid;
#pragma unroll
        for (int c = 0; c < 4; c++) {
            unsigned b = bal[it * 4 + c];
            if (b) {
                float val = (c == 0) ? v[it].x : (c == 1) ? v[it].y : (c == 2) ? v[it].z : v[it].w;
                if (val != 0.f) {
                    int p = off + __popc(b & ltmask);
                    if (p < MAXNZ) idx[p] = (short)(4 * q + c);
                }
                off += __popc(b);
            }
        }
    }
    __syncthreads();

    cudaGridDependencySynchronize();

    int h = warp;
    int grp = lane >> 3, f = lane & 7;
    const float* f1h = g_f1[g] + h * NN;
    float f2v = g_f2[g][h * NN + i];
    float Mv = fdec(g_f1maxI[g * 8 + h]) + f2v;
    Mv = Mv >= 0.f ? Mv : 0.2f * Mv;
    const float* sb = g_s[g];

    float accf = 0.f;
    float se = 0.f;
    for (int k = grp; k < m; k += 4) {
        int jj = idx[k];
        float vv = f1h[jj] + f2v;
        vv = vv >= 0.f ? vv : 0.2f * vv;
        float e = __expf(vv - Mv);
        float sv = sb[jj * HD + h * 8 + f];
        accf += e * sv;
        se += (f == 0) ? e : 0.f;
    }
    accf += __shfl_xor_sync(0xffffffffu, accf, 8);
    accf += __shfl_xor_sync(0xffffffffu, accf, 16);
    se += __shfl_xor_sync(0xffffffffu, se, 8);
    se += __shfl_xor_sync(0xffffffffu, se, 16);
    se = __shfl_sync(0xffffffffu, se, 0);
    if (lane < 8) {
        float inv = se > 0.f ? 1.0f / se : 0.f;
        g_att[g][i * HD + h * 8 + lane] = accf * inv;
    }
}

// ---------------- K4: comb with smem-staged weights (8 warps, 32 nodes/block, grid 94) ----------------
__global__ void __launch_bounds__(256) comb_kernel(
        const float* __restrict__ pos_b, const float* __restrict__ pWp, const float* __restrict__ pbp,
        const float* __restrict__ neg_b, const float* __restrict__ pWn, const float* __restrict__ pbn,
        const float* __restrict__ selfW, const float* __restrict__ selfb,
        const float* __restrict__ mpW, const float* __restrict__ mpb,
        const float* __restrict__ mnW, const float* __restrict__ mnb,
        const float* __restrict__ semW1, const float* __restrict__ semb1,
        const float* __restrict__ semW2) {
    extern __shared__ float smw[];                 // [6*HD*HD] weights | staging
    __shared__ float colacc[HD];
    int tid = threadIdx.x, warp = tid >> 5, lane = tid & 31;
    int c0 = 2 * lane, c1 = 2 * lane + 1;

    if (tid < HD) colacc[tid] = 0.f;

    {
        const float* srcs[6] = { pWp, pWn, selfW, mpW, mnW, semW1 };
#pragma unroll
        for (int mtx = 0; mtx < 6; mtx++) {
            const float4* s4 = (const float4*)srcs[mtx];
            float4* d4 = (float4*)(smw + mtx * HD * HD);
            for (int i = tid; i < HD * HD / 4; i += 256) d4[i] = s4[i];
        }
    }
    float2 pb2  = ((const float2*)pos_b)[lane];
    float2 pbp2 = ((const float2*)pbp)[lane];
    float2 nb2  = ((const float2*)neg_b)[lane];
    float2 pbn2 = ((const float2*)pbn)[lane];
    float2 sfb2 = ((const float2*)selfb)[lane];
    float2 mpb2 = ((const float2*)mpb)[lane];
    float2 mnb2 = ((const float2*)mnb)[lane];
    float2 sb12 = ((const float2*)semb1)[lane];
    float2 w22  = ((const float2*)semW2)[lane];

    cudaGridDependencySynchronize();
    __syncthreads();

    const float2* wp2 = (const float2*)(smw + 0 * HD * HD);
    const float2* wn2 = (const float2*)(smw + 1 * HD * HD);
    const float2* ws2 = (const float2*)(smw + 2 * HD * HD);
    const float2* wm2 = (const float2*)(smw + 3 * HD * HD);
    const float2* wq2 = (const float2*)(smw + 4 * HD * HD);
    const float2* w12 = (const float2*)(smw + 5 * HD * HD);
    float (*S)[HD] = (float(*)[HD])(smw + CB_WSZ + warp * 12 * HD);

    float colc0 = 0.f, colc1 = 0.f;
#pragma unroll
    for (int it = 0; it < 2; it++) {
        int nA = blockIdx.x * 32 + it * 16 + warp * 2;
        if (nA >= NN) continue;
        int nB = nA + 1;

        {
            float2 sA = ((const float2*)(g_support + nA * HD))[lane];
            float2 sB = ((const float2*)(g_support + nB * HD))[lane];
            S[0][c0] = sA.x; S[0][c1] = sA.y;
            S[1][c0] = sB.x; S[1][c1] = sB.y;
        }
        __syncwarp();

        float2 atpA = ((const float2*)(g_att[0] + nA * HD))[lane];
        float2 atpB = ((const float2*)(g_att[0] + nB * HD))[lane];
        float2 atnA = ((const float2*)(g_att[1] + nA * HD))[lane];
        float2 atnB = ((const float2*)(g_att[1] + nB * HD))[lane];
        float apA0 = atpA.x + pb2.x + pbp2.x, apA1 = atpA.y + pb2.y + pbp2.y;
        float apB0 = atpB.x + pb2.x + pbp2.x, apB1 = atpB.y + pb2.y + pbp2.y;
        float anA0 = atnA.x + nb2.x + pbn2.x, anA1 = atnA.y + nb2.y + pbn2.y;
        float anB0 = atnB.x + nb2.x + pbn2.x, anB1 = atnB.y + nb2.y + pbn2.y;
        float svA0 = sfb2.x, svA1 = sfb2.y, svB0 = sfb2.x, svB1 = sfb2.y;
#pragma unroll 8
        for (int k = 0; k < HD; k++) {
            float sA = S[0][k], sBv = S[1][k];
            float2 wp = wp2[k * 32 + lane];
            float2 wn = wn2[k * 32 + lane];
            float2 ws = ws2[k * 32 + lane];
            apA0 += sA * wp.x;  apA1 += sA * wp.y;  apB0 += sBv * wp.x;  apB1 += sBv * wp.y;
            anA0 += sA * wn.x;  anA1 += sA * wn.y;  anB0 += sBv * wn.x;  anB1 += sBv * wn.y;
            svA0 += sA * ws.x;  svA1 += sA * ws.y;  svB0 += sBv * ws.x;  svB1 += sBv * ws.y;
        }
        S[2][c0] = apA0; S[2][c1] = apA1; S[3][c0] = apB0; S[3][c1] = apB1;
        S[4][c0] = anA0; S[4][c1] = anA1; S[5][c0] = anB0; S[5][c1] = anB1;
        __syncwarp();

        float spA0 = mpb2.x, spA1 = mpb2.y, spB0 = mpb2.x, spB1 = mpb2.y;
        float snA0 = mnb2.x, snA1 = mnb2.y, snB0 = mnb2.x, snB1 = mnb2.y;
#pragma unroll 8
        for (int k = 0; k < HD; k++) {
            float pA = S[2][k], pB = S[3][k], qA = S[4][k], qB = S[5][k];
            float2 w = wm2[k * 32 + lane];
            float2 v = wq2[k * 32 + lane];
            spA0 += pA * w.x; spA1 += pA * w.y; spB0 += pB * w.x; spB1 += pB * w.y;
            snA0 += qA * v.x; snA1 += qA * v.y; snB0 += qB * v.x; snB1 += qB * v.y;
        }
        S[6][c0] = svA0; S[6][c1] = svA1; S[7][c0] = svB0; S[7][c1] = svB1;
        S[8][c0] = spA0; S[8][c1] = spA1; S[9][c0] = spB0; S[9][c1] = spB1;
        S[10][c0] = snA0; S[10][c1] = snA1; S[11][c0] = snB0; S[11][c1] = snB1;
        __syncwarp();

        float tA00 = sb12.x, tA01 = sb12.y, tA10 = sb12.x, tA11 = sb12.y, tA20 = sb12.x, tA21 = sb12.y;
        float tB00 = sb12.x, tB01 = sb12.y, tB10 = sb12.x, tB11 = sb12.y, tB20 = sb12.x, tB21 = sb12.y;
#pragma unroll 8
        for (int k = 0; k < HD; k++) {
            float2 w = w12[k * 32 + lane];
            float e0A = S[6][k], e0B = S[7][k];
            float e1A = S[8][k], e1B = S[9][k];
            float e2A = S[10][k], e2B = S[11][k];
            tA00 += e0A * w.x; tA01 += e0A * w.y; tB00 += e0B * w.x; tB01 += e0B * w.y;
            tA10 += e1A * w.x; tA11 += e1A * w.y; tB10 += e1B * w.x; tB11 += e1B * w.y;
            tA20 += e2A * w.x; tA21 += e2A * w.y; tB20 += e2B * w.x; tB21 += e2B * w.y;
        }
        float uA0 = tanhfast(tA00) * w22.x + tanhfast(tA01) * w22.y;
        float uA1 = tanhfast(tA10) * w22.x + tanhfast(tA11) * w22.y;
        float uA2 = tanhfast(tA20) * w22.x + tanhfast(tA21) * w22.y;
        float uB0 = tanhfast(tB00) * w22.x + tanhfast(tB01) * w22.y;
        float uB1 = tanhfast(tB10) * w22.x + tanhfast(tB11) * w22.y;
        float uB2 = tanhfast(tB20) * w22.x + tanhfast(tB21) * w22.y;
#pragma unroll
        for (int o = 16; o; o >>= 1) {
            uA0 += __shfl_xor_sync(0xffffffffu, uA0, o);
            uA1 += __shfl_xor_sync(0xffffffffu, uA1, o);
            uA2 += __shfl_xor_sync(0xffffffffu, uA2, o);
            uB0 += __shfl_xor_sync(0xffffffffu, uB0, o);
            uB1 += __shfl_xor_sync(0xffffffffu, uB1, o);
            uB2 += __shfl_xor_sync(0xffffffffu, uB2, o);
        }
        float mA = fmaxf(uA0, fmaxf(uA1, uA2));
        float eA0 = __expf(uA0 - mA), eA1 = __expf(uA1 - mA), eA2 = __expf(uA2 - mA);
        float invA = 1.f / (eA0 + eA1 + eA2);
        float embA0 = (eA0 * svA0 + eA1 * spA0 + eA2 * snA0) * invA;
        float embA1 = (eA0 * svA1 + eA1 * spA1 + eA2 * snA1) * invA;
        float mB = fmaxf(uB0, fmaxf(uB1, uB2));
        float eB0 = __expf(uB0 - mB), eB1 = __expf(uB1 - mB), eB2 = __expf(uB2 - mB);
        float invB = 1.f / (eB0 + eB1 + eB2);
        float embB0 = (eB0 * svB0 + eB1 * spB0 + eB2 * snB0) * invB;
        float embB1 = (eB0 * svB1 + eB1 * spB1 + eB2 * snB1) * invB;

        ((float2*)(g_emb + nA * HD))[lane] = make_float2(embA0, embA1);
        ((float2*)(g_emb + nB * HD))[lane] = make_float2(embB0, embB1);
        colc0 += embA0 + embB0;
        colc1 += embA1 + embB1;
    }
    atomicAdd(&colacc[c0], colc0);
    atomicAdd(&colacc[c1], colc1);
    __syncthreads();
    if (tid < HD) atomicAdd(&g_colsum[tid], colacc[tid]);
}

// ---------------- K5: pairnorm + prediction head (warp per node) ----------------
__global__ void final_kernel(const float* __restrict__ predW, const float* __restrict__ predb,
                             float* __restrict__ out) {
    int warp = threadIdx.x >> 5, lane = threadIdx.x & 31;
    int n = blockIdx.x * 4 + warp;
    float invn = 1.0f / NN;
    float x0 = g_emb[n * HD + lane]      - g_colsum[lane]      * invn;
    float x1 = g_emb[n * HD + 32 + lane] - g_colsum[32 + lane] * invn;
    float ss = x0 * x0 + x1 * x1;
    float dt = x0 * predW[lane] + x1 * predW[32 + lane];
#pragma unroll
    for (int o = 16; o; o >>= 1) {
        ss += __shfl_xor_sync(0xffffffffu, ss, o);
        dt += __shfl_xor_sync(0xffffffffu, dt, o);
    }
    if (lane == 0) out[n] = sigm(dt * rsqrtf(1e-6f + ss) + predb[0]);
}

// ---------------- launch (PDL on gru/attn/comb) ----------------
template <typename... Args>
static void launch_pdl(void (*kern)(Args...), dim3 grid, dim3 block, size_t smem, Args... args) {
    cudaLaunchConfig_t cfg = {};
    cfg.gridDim = grid;
    cfg.blockDim = block;
    cfg.dynamicSmemBytes = smem;
    cfg.stream = 0;
    cudaLaunchAttribute attr[1];
    attr[0].id = cudaLaunchAttributeProgrammaticStreamSerialization;
    attr[0].val.programmaticStreamSerializationAllowed = 1;
    cfg.attrs = attr;
    cfg.numAttrs = 1;
    cudaLaunchKernelEx(&cfg, kern, args...);
}

extern "C" void kernel_launch(void* const* d_in, const int* in_sizes, int n_in,
                              void* d_out, int out_size) {
    (void)in_sizes; (void)n_in; (void)out_size;
    const float* inputs   = (const float*)d_in[0];
    const float* pos_adj  = (const float*)d_in[1];
    const float* neg_adj  = (const float*)d_in[2];
    const float* Wih      = (const float*)d_in[3];
    const float* Whh      = (const float*)d_in[4];
    const float* bih      = (const float*)d_in[5];
    const float* bhh      = (const float*)d_in[6];
    const float* pos_W    = (const float*)d_in[7];
    const float* pos_Wu   = (const float*)d_in[8];
    const float* pos_Wv   = (const float*)d_in[9];
    const float* pos_b    = (const float*)d_in[10];
    const float* pos_projW= (const float*)d_in[11];
    const float* pos_projb= (const float*)d_in[12];
    const float* neg_W    = (const float*)d_in[13];
    const float* neg_Wu   = (const float*)d_in[14];
    const float* neg_Wv   = (const float*)d_in[15];
    const float* neg_b    = (const float*)d_in[16];
    const float* neg_projW= (const float*)d_in[17];
    const float* neg_projb= (const float*)d_in[18];
    const float* self_W   = (const float*)d_in[19];
    const float* self_b   = (const float*)d_in[20];
    const float* mlpp_W   = (const float*)d_in[21];
    const float* mlpp_b   = (const float*)d_in[22];
    const float* mlpn_W   = (const float*)d_in[23];
    const float* mlpn_b   = (const float*)d_in[24];
    const float* sem_W1   = (const float*)d_in[25];
    const float* sem_b1   = (const float*)d_in[26];
    const float* sem_W2   = (const float*)d_in[27];
    const float* pred_W   = (const float*)d_in[28];
    const float* pred_b   = (const float*)d_in[29];

    static int attr_set = 0;
    if (!attr_set) {
        cudaFuncSetAttribute(comb_kernel, cudaFuncAttributeMaxDynamicSharedMemorySize, CB_SMEM);
        attr_set = 1;
    }

    prep_kernel<<<48, 256>>>(Whh);
    launch_pdl(gru_kernel, dim3(NN / 4), dim3(64), 0,
               inputs, Wih, bih, bhh,
               pos_W, neg_W, pos_Wu, pos_Wv, neg_Wu, neg_Wv);
    launch_pdl(attn_kernel, dim3(NN, 2), dim3(256), 0, pos_adj, neg_adj);
    launch_pdl(comb_kernel, dim3((NN + 31) / 32), dim3(256), (size_t)CB_SMEM,
               pos_b, pos_projW, pos_projb, neg_b, neg_projW, neg_projb,
               self_W, self_b, mlpp_W, mlpp_b, mlpn_W, mlpn_b,
               sem_W1, sem_b1, sem_W2);
    final_kernel<<<NN / 4, 128>>>(pred_W, pred_b, (float*)d_out);
}

// round 17
// speedup vs baseline: 1.1608x; 1.0158x over previous
#include <cuda_runtime.h>

#define NN 3000
#define TT 20
#define IND 6
#define HD 64
#define NH 8
#define MAXNZ 512

#define CB_WARPS 8
#define CB_WSZ  (6 * HD * HD)                       // 24576 floats of weights
#define CB_SMEM ((CB_WSZ + CB_WARPS * 12 * HD) * 4) // 120 KB

// ---------------- scratch (no allocation allowed) ----------------
__device__ float4 g_WA[(HD / 2) * HD];      // [p*64+j] = (wr_k, wr_k+1, wz_k, wz_k+1)
__device__ float2 g_WB[(HD / 2) * HD];      // [p*64+j] = (wn_k, wn_k+1)
__device__ float g_support[NN * HD];        // GRU final hidden
__device__ float g_s[2][NN * HD];           // per-graph head features  [n][h*8+f]
__device__ float g_f1[2][NH * NN];          // source scores  [g][h*N+n]
__device__ float g_f2[2][NH * NN];          // dest scores    [g][h*N+n]
__device__ unsigned g_f1maxI[16];           // encoded global per-(g,h) max of f1
__device__ float g_att[2][NN * HD];         // attention outputs
__device__ float g_emb[NN * HD];            // pre-pairnorm embedding
__device__ float g_colsum[HD];              // column sums for pairnorm mean

__device__ __forceinline__ float sigm(float x) { return 1.0f / (1.0f + __expf(-x)); }
__device__ __forceinline__ float tanhfast(float x) { return 2.0f * sigm(2.0f * x) - 1.0f; }

__device__ __forceinline__ unsigned fenc(float f) {
    unsigned u = __float_as_uint(f);
    return (u & 0x80000000u) ? ~u : (u | 0x80000000u);
}
__device__ __forceinline__ float fdec(unsigned u) {
    return __uint_as_float((u & 0x80000000u) ? (u & 0x7fffffffu) : ~u);
}

__device__ __forceinline__ unsigned long long pk(float lo, float hi) {
    unsigned long long r;
    asm("mov.b64 %0, {%1,%2};" : "=l"(r) : "f"(lo), "f"(hi));
    return r;
}
__device__ __forceinline__ void upk(unsigned long long v, float& lo, float& hi) {
    asm("mov.b64 {%0,%1}, %2;" : "=f"(lo), "=f"(hi) : "l"(v));
}
__device__ __forceinline__ void ffma2(unsigned long long& d, unsigned long long a, unsigned long long b) {
    asm("fma.rn.f32x2 %0, %1, %2, %0;" : "+l"(d) : "l"(a), "l"(b));
}

// ---------------- K0: natural-layout weight repack + init reductions ----------------
__global__ void prep_kernel(const float* __restrict__ Whh) {
    int i = blockIdx.x * 256 + threadIdx.x;
    if (i < 192 * HD) {
        int r = i >> 6, k = i & 63;
        float w = Whh[i];
        int gate = r >> 6;            // 0=r, 1=z, 2=n
        int j = r & 63;
        int p = k >> 1, odd = k & 1;
        if (gate == 0)      *(&g_WA[p * 64 + j].x + odd) = w;
        else if (gate == 1) *(&g_WA[p * 64 + j].z + odd) = w;
        else                *(&g_WB[p * 64 + j].x + odd) = w;
    }
    if (blockIdx.x == 0 && threadIdx.x < HD) g_colsum[threadIdx.x] = 0.f;
    if (blockIdx.x == 0 && threadIdx.x < 16) g_f1maxI[threadIdx.x] = 0u;
}

// ---------------- K1: GRU (4 nodes / 64-thread block), natural-weight loads + reg duplication ----------------
__global__ void __launch_bounds__(64) gru_kernel(
        const float* __restrict__ x, const float* __restrict__ Wih,
        const float* __restrict__ bih, const float* __restrict__ bhh,
        const float* __restrict__ Wp, const float* __restrict__ Wn,
        const float* __restrict__ Wup, const float* __restrict__ Wvp,
        const float* __restrict__ Wun, const float* __restrict__ Wvn) {
    __shared__ float4 shh4[2][HD];      // ping-pong: [buf][k] -> 4 nodes hidden
    __shared__ float shx[TT * IND * 4]; // [ (t*6+c)*4 + b ]
    int j = threadIdx.x;
    int node0 = blockIdx.x * 4;         // 750 blocks

#pragma unroll
    for (int e = j; e < TT * IND * 4; e += 64) {
        int b = e / (TT * IND), rem = e % (TT * IND);
        shx[rem * 4 + b] = x[node0 * (TT * IND) + e];
    }

    unsigned long long pwr[IND], pwz[IND], pwn[IND];
#pragma unroll
    for (int c = 0; c < IND; c++) {
        float a = Wih[j * IND + c];
        float b = Wih[(64 + j) * IND + c];
        float d = Wih[(128 + j) * IND + c];
        pwr[c] = pk(a, a); pwz[c] = pk(b, b); pwn[c] = pk(d, d);
    }
    float br  = bih[j] + bhh[j];
    float bz  = bih[64 + j] + bhh[64 + j];
    float bin = bih[128 + j];
    float bhn = bhh[128 + j];
    unsigned long long pbr = pk(br, br), pbz = pk(bz, bz);
    unsigned long long pbi = pk(bin, bin), pbh = pk(bhn, bhn);

    shh4[0][j] = make_float4(0.f, 0.f, 0.f, 0.f);
    float h0 = 0.f, h1 = 0.f, h2 = 0.f, h3 = 0.f;
    int cur = 0;

    cudaGridDependencySynchronize();    // g_WA/g_WB ready (prep done)
    __syncthreads();

    for (int t = 0; t < TT; t++) {
        const float4* xt = (const float4*)(shx + t * IND * 4);

        unsigned long long ar01 = pbr, ar23 = pbr;
        unsigned long long az01 = pbz, az23 = pbz;
        unsigned long long an01 = pbi, an23 = pbi;
        unsigned long long gn01 = pbh, gn23 = pbh;

#pragma unroll
        for (int c = 0; c < IND; c++) {
            float4 xv = xt[c];
            unsigned long long x01 = pk(xv.x, xv.y), x23 = pk(xv.z, xv.w);
            ffma2(ar01, pwr[c], x01); ffma2(ar23, pwr[c], x23);
            ffma2(az01, pwz[c], x01); ffma2(az23, pwz[c], x23);
            ffma2(an01, pwn[c], x01); ffma2(an23, pwn[c], x23);
        }

        const float4* hbuf = shh4[cur];
#pragma unroll 4
        for (int p = 0; p < HD / 2; p++) {
            float4 hva = hbuf[2 * p], hvb = hbuf[2 * p + 1];
            unsigned long long ha01 = pk(hva.x, hva.y), ha23 = pk(hva.z, hva.w);
            unsigned long long hb01 = pk(hvb.x, hvb.y), hb23 = pk(hvb.z, hvb.w);
            float4 wa = g_WA[p * 64 + j];
            float2 wb = g_WB[p * 64 + j];
            unsigned long long wrx = pk(wa.x, wa.x), wry = pk(wa.y, wa.y);
            unsigned long long wzx = pk(wa.z, wa.z), wzy = pk(wa.w, wa.w);
            unsigned long long wnx = pk(wb.x, wb.x), wny = pk(wb.y, wb.y);
            ffma2(ar01, wrx, ha01);  ffma2(ar23, wrx, ha23);
            ffma2(az01, wzx, ha01);  ffma2(az23, wzx, ha23);
            ffma2(gn01, wnx, ha01);  ffma2(gn23, wnx, ha23);
            ffma2(ar01, wry, hb01);  ffma2(ar23, wry, hb23);
            ffma2(az01, wzy, hb01);  ffma2(az23, wzy, hb23);
            ffma2(gn01, wny, hb01);  ffma2(gn23, wny, hb23);
        }

        float a0, a1, a2, a3, z0, z1, z2, z3, n0, n1, n2, n3, g0, g1, g2, g3;
        upk(ar01, a0, a1); upk(ar23, a2, a3);
        upk(az01, z0, z1); upk(az23, z2, z3);
        upk(an01, n0, n1); upk(an23, n2, n3);
        upk(gn01, g0, g1); upk(gn23, g2, g3);

        float r0 = sigm(a0), r1 = sigm(a1), r2 = sigm(a2), r3 = sigm(a3);
        float zz0 = sigm(z0), zz1 = sigm(z1), zz2 = sigm(z2), zz3 = sigm(z3);
        float nv0 = tanhfast(n0 + r0 * g0);
        float nv1 = tanhfast(n1 + r1 * g1);
        float nv2 = tanhfast(n2 + r2 * g2);
        float nv3 = tanhfast(n3 + r3 * g3);
        h0 = (1.f - zz0) * nv0 + zz0 * h0;
        h1 = (1.f - zz1) * nv1 + zz1 * h1;
        h2 = (1.f - zz2) * nv2 + zz2 * h2;
        h3 = (1.f - zz3) * nv3 + zz3 * h3;
        shh4[cur ^ 1][j] = make_float4(h0, h1, h2, h3);
        __syncthreads();
        cur ^= 1;
    }

    g_support[(node0 + 0) * HD + j] = h0;
    g_support[(node0 + 1) * HD + j] = h1;
    g_support[(node0 + 2) * HD + j] = h2;
    g_support[(node0 + 3) * HD + j] = h3;

    // fused head projection: s = h @ W, f1/f2, global f1 max
    int hh = j >> 3, f = j & 7;
    const float* hsm = (const float*)shh4[cur];
#pragma unroll
    for (int g = 0; g < 2; g++) {
        const float* W  = g ? Wn  : Wp;
        float wu = (g ? Wun : Wup)[hh * 8 + f];
        float wv = (g ? Wvn : Wvp)[hh * 8 + f];
        float acc[4] = {0.f, 0.f, 0.f, 0.f};
#pragma unroll 4
        for (int k = 0; k < HD; k++) {
            float w = W[k * HD + j];
#pragma unroll
            for (int b = 0; b < 4; b++) acc[b] += hsm[k * 4 + b] * w;
        }
#pragma unroll
        for (int b = 0; b < 4; b++) {
            int n = node0 + b;
            g_s[g][n * HD + j] = acc[b];
            float t1 = acc[b] * wu, t2 = acc[b] * wv;
#pragma unroll
            for (int o = 4; o; o >>= 1) {
                t1 += __shfl_xor_sync(0xffffffffu, t1, o);
                t2 += __shfl_xor_sync(0xffffffffu, t2, o);
            }
            if (f == 0) {
                g_f1[g][hh * NN + n] = t1;
                g_f2[g][hh * NN + n] = t2;
                atomicMax(&g_f1maxI[g * 8 + hh], fenc(t1));
            }
        }
    }
}

// ---------------- K3: sparse masked attention; compaction overlapped with GRU via PDL ----------------
__global__ void attn_kernel(const float* __restrict__ adj0, const float* __restrict__ adj1) {
    int i = blockIdx.x, g = blockIdx.y;
    const float* row = (g ? adj1 : adj0) + (size_t)i * NN;
    __shared__ short idx[MAXNZ];
    __shared__ int cnts[8];
    int tid = threadIdx.x, warp = tid >> 5, lane = tid & 31;

    const float4* row4 = (const float4*)row;
    float4 v[3];
#pragma unroll
    for (int it = 0; it < 3; it++) {
        int q = it * 256 + tid;
        v[it] = (q < NN / 4) ? row4[q] : make_float4(0.f, 0.f, 0.f, 0.f);
    }

    unsigned bal[12];
    int wcnt = 0;
#pragma unroll
    for (int it = 0; it < 3; it++) {
#pragma unroll
        for (int c = 0; c < 4; c++) {
            float val = (c == 0) ? v[it].x : (c == 1) ? v[it].y : (c == 2) ? v[it].z : v[it].w;
            unsigned b = __ballot_sync(0xffffffffu, val != 0.f);
            bal[it * 4 + c] = b;
            wcnt += __popc(b);
        }
    }
    if (lane == 0) cnts[warp] = wcnt;
    __syncthreads();

    int base = 0, m = 0;
#pragma unroll
    for (int s = 0; s < 8; s++) {
        int cs = cnts[s];
        if (s < warp) base += cs;
        m += cs;
    }
    m = min(m, MAXNZ);

    unsigned ltmask = (1u << lane) - 1u;
    int off = base;
#pragma unroll
    for (int it = 0; it < 3; it++) {
        int q = it * 256 + tid;
#pragma unroll
        for (int c = 0; c < 4; c++) {
            unsigned b = bal[it * 4 + c];
            if (b) {
                float val = (c == 0) ? v[it].x : (c == 1) ? v[it].y : (c == 2) ? v[it].z : v[it].w;
                if (val != 0.f) {
                    int p = off + __popc(b & ltmask);
                    if (p < MAXNZ) idx[p] = (short)(4 * q + c);
                }
                off += __popc(b);
            }
        }
    }
    __syncthreads();

    cudaGridDependencySynchronize();

    int h = warp;
    int grp = lane >> 3, f = lane & 7;
    const float* f1h = g_f1[g] + h * NN;
    float f2v = g_f2[g][h * NN + i];
    float Mv = fdec(g_f1maxI[g * 8 + h]) + f2v;
    Mv = Mv >= 0.f ? Mv : 0.2f * Mv;
    const float* sb = g_s[g];

    float accf = 0.f;
    float se = 0.f;
    for (int k = grp; k < m; k += 4) {
        int jj = idx[k];
        float vv = f1h[jj] + f2v;
        vv = vv >= 0.f ? vv : 0.2f * vv;
        float e = __expf(vv - Mv);
        float sv = sb[jj * HD + h * 8 + f];
        accf += e * sv;
        se += (f == 0) ? e : 0.f;
    }
    accf += __shfl_xor_sync(0xffffffffu, accf, 8);
    accf += __shfl_xor_sync(0xffffffffu, accf, 16);
    se += __shfl_xor_sync(0xffffffffu, se, 8);
    se += __shfl_xor_sync(0xffffffffu, se, 16);
    se = __shfl_sync(0xffffffffu, se, 0);
    if (lane < 8) {
        float inv = se > 0.f ? 1.0f / se : 0.f;
        g_att[g][i * HD + h * 8 + lane] = accf * inv;
    }
}

// ---------------- K4: comb, 4 nodes/warp (32 nodes/block, grid 94), smem-staged weights ----------------
__global__ void __launch_bounds__(256) comb_kernel(
        const float* __restrict__ pos_b, const float* __restrict__ pWp, const float* __restrict__ pbp,
        const float* __restrict__ neg_b, const float* __restrict__ pWn, const float* __restrict__ pbn,
        const float* __restrict__ selfW, const float* __restrict__ selfb,
        const float* __restrict__ mpW, const float* __restrict__ mpb,
        const float* __restrict__ mnW, const float* __restrict__ mnb,
        const float* __restrict__ semW1, const float* __restrict__ semb1,
        const float* __restrict__ semW2) {
    extern __shared__ float smw[];                 // [6*HD*HD] weights | per-warp staging
    __shared__ float colacc[HD];
    int tid = threadIdx.x, warp = tid >> 5, lane = tid & 31;
    int c0 = 2 * lane, c1 = 2 * lane + 1;

    if (tid < HD) colacc[tid] = 0.f;

    // pre-sync: stage all six 64x64 weight matrices into smem
    {
        const float* srcs[6] = { pWp, pWn, selfW, mpW, mnW, semW1 };
#pragma unroll
        for (int mtx = 0; mtx < 6; mtx++) {
            const float4* s4 = (const float4*)srcs[mtx];
            float4* d4 = (float4*)(smw + mtx * HD * HD);
            for (int i = tid; i < HD * HD / 4; i += 256) d4[i] = s4[i];
        }
    }
    float2 pb2  = ((const float2*)pos_b)[lane];
    float2 pbp2 = ((const float2*)pbp)[lane];
    float2 nb2  = ((const float2*)neg_b)[lane];
    float2 pbn2 = ((const float2*)pbn)[lane];
    float2 sfb2 = ((const float2*)selfb)[lane];
    float2 mpb2 = ((const float2*)mpb)[lane];
    float2 mnb2 = ((const float2*)mnb)[lane];
    float2 sb12 = ((const float2*)semb1)[lane];
    float2 w22  = ((const float2*)semW2)[lane];

    cudaGridDependencySynchronize();
    __syncthreads();

    const float2* wp2 = (const float2*)(smw + 0 * HD * HD);
    const float2* wn2 = (const float2*)(smw + 1 * HD * HD);
    const float2* ws2 = (const float2*)(smw + 2 * HD * HD);
    const float2* wm2 = (const float2*)(smw + 3 * HD * HD);
    const float2* wq2 = (const float2*)(smw + 4 * HD * HD);
    const float2* w12 = (const float2*)(smw + 5 * HD * HD);
    float (*S)[HD] = (float(*)[HD])(smw + CB_WSZ + warp * 12 * HD);

    int nA = blockIdx.x * 32 + warp * 4;     // 94*32=3008; skip tail warps
    float colc0 = 0.f, colc1 = 0.f;
    if (nA < NN) {                           // NN%4==0 -> all 4 nodes valid
        // ---- load 4 support vectors into S[0..3] ----
#pragma unroll
        for (int b = 0; b < 4; b++) {
            float2 sv2 = ((const float2*)(g_support + (nA + b) * HD))[lane];
            S[b][c0] = sv2.x; S[b][c1] = sv2.y;
        }
        __syncwarp();

        // ---- phase 1: ap/an/sv for 4 nodes ----
        float ap0[4], ap1[4], an0[4], an1[4], sv0[4], sv1[4];
#pragma unroll
        for (int b = 0; b < 4; b++) {
            float2 atp = ((const float2*)(g_att[0] + (nA + b) * HD))[lane];
            float2 atn = ((const float2*)(g_att[1] + (nA + b) * HD))[lane];
            ap0[b] = atp.x + pb2.x + pbp2.x; ap1[b] = atp.y + pb2.y + pbp2.y;
            an0[b] = atn.x + nb2.x + pbn2.x; an1[b] = atn.y + nb2.y + pbn2.y;
            sv0[b] = sfb2.x; sv1[b] = sfb2.y;
        }
#pragma unroll 4
        for (int k = 0; k < HD; k++) {
            float s0 = S[0][k], s1 = S[1][k], s2 = S[2][k], s3 = S[3][k];
            float2 wp = wp2[k * 32 + lane];
            float2 wn = wn2[k * 32 + lane];
            float2 ws = ws2[k * 32 + lane];
            ap0[0] += s0 * wp.x; ap1[0] += s0 * wp.y; ap0[1] += s1 * wp.x; ap1[1] += s1 * wp.y;
            ap0[2] += s2 * wp.x; ap1[2] += s2 * wp.y; ap0[3] += s3 * wp.x; ap1[3] += s3 * wp.y;
            an0[0] += s0 * wn.x; an1[0] += s0 * wn.y; an0[1] += s1 * wn.x; an1[1] += s1 * wn.y;
            an0[2] += s2 * wn.x; an1[2] += s2 * wn.y; an0[3] += s3 * wn.x; an1[3] += s3 * wn.y;
            sv0[0] += s0 * ws.x; sv1[0] += s0 * ws.y; sv0[1] += s1 * ws.x; sv1[1] += s1 * ws.y;
            sv0[2] += s2 * ws.x; sv1[2] += s2 * ws.y; sv0[3] += s3 * ws.x; sv1[3] += s3 * ws.y;
        }
        __syncwarp();     // S[0..3] reads done; reuse below
#pragma unroll
        for (int b = 0; b < 4; b++) {
            S[4 + b][c0] = ap0[b]; S[4 + b][c1] = ap1[b];   // ps
            S[8 + b][c0] = an0[b]; S[8 + b][c1] = an1[b];   // ns
        }
        __syncwarp();

        // ---- phase 2: sp/sn for 4 nodes ----
        float sp0[4], sp1[4], sn0[4], sn1[4];
#pragma unroll
        for (int b = 0; b < 4; b++) { sp0[b] = mpb2.x; sp1[b] = mpb2.y; sn0[b] = mnb2.x; sn1[b] = mnb2.y; }
#pragma unroll 4
        for (int k = 0; k < HD; k++) {
            float p0 = S[4][k], p1 = S[5][k], p2 = S[6][k], p3 = S[7][k];
            float q0 = S[8][k], q1 = S[9][k], q2 = S[10][k], q3 = S[11][k];
            float2 w = wm2[k * 32 + lane];
            float2 v = wq2[k * 32 + lane];
            sp0[0] += p0 * w.x; sp1[0] += p0 * w.y; sp0[1] += p1 * w.x; sp1[1] += p1 * w.y;
            sp0[2] += p2 * w.x; sp1[2] += p2 * w.y; sp0[3] += p3 * w.x; sp1[3] += p3 * w.y;
            sn0[0] += q0 * v.x; sn1[0] += q0 * v.y; sn0[1] += q1 * v.x; sn1[1] += q1 * v.y;
            sn0[2] += q2 * v.x; sn1[2] += q2 * v.y; sn0[3] += q3 * v.x; sn1[3] += q3 * v.y;
        }
        __syncwarp();     // ps/ns reads done; reuse all 12 buffers for e0/e1/e2
#pragma unroll
        for (int b = 0; b < 4; b++) {
            S[b][c0]     = sv0[b]; S[b][c1]     = sv1[b];   // e0
            S[4 + b][c0] = sp0[b]; S[4 + b][c1] = sp1[b];   // e1
            S[8 + b][c0] = sn0[b]; S[8 + b][c1] = sn1[b];   // e2
        }
        __syncwarp();

        // ---- phase 3 (two halves of 2 nodes) + epilogue ----
#pragma unroll
        for (int half = 0; half < 2; half++) {
            int bA = half * 2, bB = half * 2 + 1;
            float tA0 = sb12.x, tA0y = sb12.y, tA1 = sb12.x, tA1y = sb12.y, tA2 = sb12.x, tA2y = sb12.y;
            float tB0 = sb12.x, tB0y = sb12.y, tB1 = sb12.x, tB1y = sb12.y, tB2 = sb12.x, tB2y = sb12.y;
#pragma unroll 4
            for (int k = 0; k < HD; k++) {
                float2 w = w12[k * 32 + lane];
                float e0A = S[bA][k], e0B = S[bB][k];
                float e1A = S[4 + bA][k], e1B = S[4 + bB][k];
                float e2A = S[8 + bA][k], e2B = S[8 + bB][k];
                tA0 += e0A * w.x; tA0y += e0A * w.y; tB0 += e0B * w.x; tB0y += e0B * w.y;
                tA1 += e1A * w.x; tA1y += e1A * w.y; tB1 += e1B * w.x; tB1y += e1B * w.y;
                tA2 += e2A * w.x; tA2y += e2A * w.y; tB2 += e2B * w.x; tB2y += e2B * w.y;
            }
            float uA0 = tanhfast(tA0) * w22.x + tanhfast(tA0y) * w22.y;
            float uA1 = tanhfast(tA1) * w22.x + tanhfast(tA1y) * w22.y;
            float uA2 = tanhfast(tA2) * w22.x + tanhfast(tA2y) * w22.y;
            float uB0 = tanhfast(tB0) * w22.x + tanhfast(tB0y) * w22.y;
            float uB1 = tanhfast(tB1) * w22.x + tanhfast(tB1y) * w22.y;
            float uB2 = tanhfast(tB2) * w22.x + tanhfast(tB2y) * w22.y;
#pragma unroll
            for (int o = 16; o; o >>= 1) {
                uA0 += __shfl_xor_sync(0xffffffffu, uA0, o);
                uA1 += __shfl_xor_sync(0xffffffffu, uA1, o);
                uA2 += __shfl_xor_sync(0xffffffffu, uA2, o);
                uB0 += __shfl_xor_sync(0xffffffffu, uB0, o);
                uB1 += __shfl_xor_sync(0xffffffffu, uB1, o);
                uB2 += __shfl_xor_sync(0xffffffffu, uB2, o);
            }
            float mA = fmaxf(uA0, fmaxf(uA1, uA2));
            float eA0 = __expf(uA0 - mA), eA1 = __expf(uA1 - mA), eA2 = __expf(uA2 - mA);
            float invA = 1.f / (eA0 + eA1 + eA2);
            float embA0 = (eA0 * sv0[bA] + eA1 * sp0[bA] + eA2 * sn0[bA]) * invA;
            float embA1 = (eA0 * sv1[bA] + eA1 * sp1[bA] + eA2 * sn1[bA]) * invA;
            float mB = fmaxf(uB0, fmaxf(uB1, uB2));
            float eB0 = __expf(uB0 - mB), eB1 = __expf(uB1 - mB), eB2 = __expf(uB2 - mB);
            float invB = 1.f / (eB0 + eB1 + eB2);
            float embB0 = (eB0 * sv0[bB] + eB1 * sp0[bB] + eB2 * sn0[bB]) * invB;
            float embB1 = (eB0 * sv1[bB] + eB1 * sp1[bB] + eB2 * sn1[bB]) * invB;

            ((float2*)(g_emb + (nA + bA) * HD))[lane] = make_float2(embA0, embA1);
            ((float2*)(g_emb + (nA + bB) * HD))[lane] = make_float2(embB0, embB1);
            colc0 += embA0 + embB0;
            colc1 += embA1 + embB1;
        }
    }
    atomicAdd(&colacc[c0], colc0);
    atomicAdd(&colacc[c1], colc1);
    __syncthreads();
    if (tid < HD) atomicAdd(&g_colsum[tid], colacc[tid]);
}

// ---------------- K5: pairnorm + prediction head (warp per node) ----------------
__global__ void final_kernel(const float* __restrict__ predW, const float* __restrict__ predb,
                             float* __restrict__ out) {
    int warp = threadIdx.x >> 5, lane = threadIdx.x & 31;
    int n = blockIdx.x * 4 + warp;
    float invn = 1.0f / NN;
    float x0 = g_emb[n * HD + lane]      - g_colsum[lane]      * invn;
    float x1 = g_emb[n * HD + 32 + lane] - g_colsum[32 + lane] * invn;
    float ss = x0 * x0 + x1 * x1;
    float dt = x0 * predW[lane] + x1 * predW[32 + lane];
#pragma unroll
    for (int o = 16; o; o >>= 1) {
        ss += __shfl_xor_sync(0xffffffffu, ss, o);
        dt += __shfl_xor_sync(0xffffffffu, dt, o);
    }
    if (lane == 0) out[n] = sigm(dt * rsqrtf(1e-6f + ss) + predb[0]);
}

// ---------------- launch (PDL on gru/attn/comb) ----------------
template <typename... Args>
static void launch_pdl(void (*kern)(Args...), dim3 grid, dim3 block, size_t smem, Args... args) {
    cudaLaunchConfig_t cfg = {};
    cfg.gridDim = grid;
    cfg.blockDim = block;
    cfg.dynamicSmemBytes = smem;
    cfg.stream = 0;
    cudaLaunchAttribute attr[1];
    attr[0].id = cudaLaunchAttributeProgrammaticStreamSerialization;
    attr[0].val.programmaticStreamSerializationAllowed = 1;
    cfg.attrs = attr;
    cfg.numAttrs = 1;
    cudaLaunchKernelEx(&cfg, kern, args...);
}

extern "C" void kernel_launch(void* const* d_in, const int* in_sizes, int n_in,
                              void* d_out, int out_size) {
    (void)in_sizes; (void)n_in; (void)out_size;
    const float* inputs   = (const float*)d_in[0];
    const float* pos_adj  = (const float*)d_in[1];
    const float* neg_adj  = (const float*)d_in[2];
    const float* Wih      = (const float*)d_in[3];
    const float* Whh      = (const float*)d_in[4];
    const float* bih      = (const float*)d_in[5];
    const float* bhh      = (const float*)d_in[6];
    const float* pos_W    = (const float*)d_in[7];
    const float* pos_Wu   = (const float*)d_in[8];
    const float* pos_Wv   = (const float*)d_in[9];
    const float* pos_b    = (const float*)d_in[10];
    const float* pos_projW= (const float*)d_in[11];
    const float* pos_projb= (const float*)d_in[12];
    const float* neg_W    = (const float*)d_in[13];
    const float* neg_Wu   = (const float*)d_in[14];
    const float* neg_Wv   = (const float*)d_in[15];
    const float* neg_b    = (const float*)d_in[16];
    const float* neg_projW= (const float*)d_in[17];
    const float* neg_projb= (const float*)d_in[18];
    const float* self_W   = (const float*)d_in[19];
    const float* self_b   = (const float*)d_in[20];
    const float* mlpp_W   = (const float*)d_in[21];
    const float* mlpp_b   = (const float*)d_in[22];
    const float* mlpn_W   = (const float*)d_in[23];
    const float* mlpn_b   = (const float*)d_in[24];
    const float* sem_W1   = (const float*)d_in[25];
    const float* sem_b1   = (const float*)d_in[26];
    const float* sem_W2   = (const float*)d_in[27];
    const float* pred_W   = (const float*)d_in[28];
    const float* pred_b   = (const float*)d_in[29];

    static int attr_set = 0;
    if (!attr_set) {
        cudaFuncSetAttribute(comb_kernel, cudaFuncAttributeMaxDynamicSharedMemorySize, CB_SMEM);
        attr_set = 1;
    }

    prep_kernel<<<48, 256>>>(Whh);
    launch_pdl(gru_kernel, dim3(NN / 4), dim3(64), 0,
               inputs, Wih, bih, bhh,
               pos_W, neg_W, pos_Wu, pos_Wv, neg_Wu, neg_Wv);
    launch_pdl(attn_kernel, dim3(NN, 2), dim3(256), 0, pos_adj, neg_adj);
    launch_pdl(comb_kernel, dim3((NN + 31) / 32), dim3(256), (size_t)CB_SMEM,
               pos_b, pos_projW, pos_projb, neg_b, neg_projW, neg_projb,
               self_W, self_b, mlpp_W, mlpp_b, mlpn_W, mlpn_b,
               sem_W1, sem_b1, sem_W2);
    final_kernel<<<NN / 4, 128>>>(pred_W, pred_b, (float*)d_out);
}